// round 16
// baseline (speedup 1.0000x reference)
#include <cuda_runtime.h>
#include <cuda_fp16.h>

// ---------------- problem constants ----------------
#define TOK    4096        // BATCH*SEQLEN
#define DMODEL 2048
#define DINNER 4096
#define NH     64
#define HD     64
#define NST    128
#define CDIM   4352        // DINNER + 2*NST
#define DPROJ  8512        // 2*DINNER + 2*NST + NH
#define SEQ    2048
#define CK     256         // chunk length
#define NCC    16          // BATCH * (SEQ/CK) total chunks

// ---------------- scratch (device globals; no allocation) ----------------
__device__ __align__(16) float  g_zx  [(size_t)TOK*DPROJ];
__device__ __align__(16) float  g_xbc [(size_t)TOK*CDIM];
__device__ __align__(16) float  g_dtv [(size_t)TOK*NH];
__device__ __align__(16) float  g_dacs[(size_t)NCC*NH*CK];
__device__ __align__(16) float  g_cb  [(size_t)NCC*CK*CK];
__device__ __align__(16) float  g_st  [(size_t)NCC*NH*HD*NST];
__device__ __align__(16) float  g_pv  [(size_t)NCC*NH*HD*NST];
__device__ __align__(16) float  g_y   [(size_t)TOK*DINNER];
__device__ __align__(16) __half g_uh  [(size_t)TOK*DMODEL];
__device__ __align__(16) __half g_winh[(size_t)DPROJ*DMODEL];
__device__ __align__(16) __half g_wouth[(size_t)DMODEL*DINNER];
__device__ __align__(16) __half g_bch [(size_t)TOK*2*NST];
__device__ __align__(16) __half g_yh  [(size_t)TOK*DINNER];

// ---------------- helpers ----------------
__device__ __forceinline__ unsigned f2h2(float lo, float hi) {
    __half2 h = __floats2half2_rn(lo, hi);
    return *(unsigned*)&h;
}
__device__ __forceinline__ void mma_h16(float& c0, float& c1, float& c2, float& c3,
                                        unsigned a0, unsigned a1, unsigned a2, unsigned a3,
                                        unsigned b0, unsigned b1) {
    asm volatile("mma.sync.aligned.m16n8k16.row.col.f32.f16.f16.f32 "
                 "{%0,%1,%2,%3}, {%4,%5,%6,%7}, {%8,%9}, {%0,%1,%2,%3};"
                 : "+f"(c0), "+f"(c1), "+f"(c2), "+f"(c3)
                 : "r"(a0), "r"(a1), "r"(a2), "r"(a3), "r"(b0), "r"(b1));
}
__device__ __forceinline__ void ldsm_x4(unsigned& r0, unsigned& r1, unsigned& r2,
                                        unsigned& r3, unsigned addr) {
    asm volatile("ldmatrix.sync.aligned.m8n8.x4.shared.b16 {%0,%1,%2,%3}, [%4];"
                 : "=r"(r0), "=r"(r1), "=r"(r2), "=r"(r3) : "r"(addr));
}
__device__ __forceinline__ float fsilu(float v) {
    return v * __fdividef(1.f, 1.f + __expf(-v));
}

// ---------------- fp32 -> fp16 convert (vectorized) ----------------
__global__ void k_cvt(const float* __restrict__ in, __half* __restrict__ out, int n4)
{
    int i = blockIdx.x * 256 + threadIdx.x;
    if (i >= n4) return;
    float4 v = ((const float4*)in)[i];
    ((uint2*)out)[i] = make_uint2(f2h2(v.x, v.y), f2h2(v.z, v.w));
}

// ------- fp16-NATIVE GEMM, ldmatrix frags, WARP TILE 64x64 (4 warps/CTA) -------
// BM=128, BN=128, BK=16, 128 threads. Reads/MMA: 128B (was 192B).
// HSTR=12 (48B row stride) is LDSM-conflict-free.
#define HSTR 12
__global__ __launch_bounds__(128) void gemm_h16n(
    const __half* __restrict__ A, const __half* __restrict__ B, float* __restrict__ C,
    int K, int lda, int ldb, int ldc, int N, long aB, long bB, long cB)
{
    const __half* Ab = A + (long)blockIdx.z * aB;
    const __half* Bb = B + (long)blockIdx.z * bB;
    float*        Cb = C + (long)blockIdx.z * cB;

    __shared__ unsigned As[2][128 * HSTR];
    __shared__ unsigned Bs[2][128 * HSTR];

    int tid  = threadIdx.x;
    int wid  = tid >> 5, lane = tid & 31;
    int g    = lane >> 2, tig = lane & 3;
    int wm   = wid & 1, wn = wid >> 1;          // 2 m-warps x 2 n-warps; warp tile 64x64
    int m0   = blockIdx.y * 128, n0 = blockIdx.x * 128;

    // loader: each thread owns one row (A and B), 16 halves (2x uint4) per iter
    const __half* aptr = Ab + (long)(m0 + tid) * lda;
    int bR = n0 + tid; if (bR >= N) bR = N - 1;
    const __half* bptr = Bb + (long)bR * ldb;

    unsigned asBase = (unsigned)__cvta_generic_to_shared(&As[0][0]);
    unsigned bsBase = (unsigned)__cvta_generic_to_shared(&Bs[0][0]);
    unsigned aLd = ((unsigned)((wm * 64 + ((lane >> 3) & 1) * 8 + (lane & 7)) * HSTR
                               + (lane >> 4) * 4)) * 4u;
    unsigned bLd = ((unsigned)((wn * 64 + ((lane >> 4) & 1) * 8 + (lane & 7)) * HSTR
                               + ((lane >> 3) & 1) * 4)) * 4u;
    const unsigned STGB = 128 * HSTR * 4;

    float acc[4][8][4];
#pragma unroll
    for (int i = 0; i < 4; i++)
#pragma unroll
        for (int j = 0; j < 8; j++)
#pragma unroll
            for (int r = 0; r < 4; r++) acc[i][j][r] = 0.f;

    uint4 ra0 = *(const uint4*)(aptr);
    uint4 ra1 = *(const uint4*)(aptr + 8);
    uint4 rb0 = *(const uint4*)(bptr);
    uint4 rb1 = *(const uint4*)(bptr + 8);
    *(uint4*)(As[0] + tid * HSTR)     = ra0;
    *(uint4*)(As[0] + tid * HSTR + 4) = ra1;
    *(uint4*)(Bs[0] + tid * HSTR)     = rb0;
    *(uint4*)(Bs[0] + tid * HSTR + 4) = rb1;
    __syncthreads();

    int cur = 0;
    for (int k0 = 0; k0 < K; k0 += 16) {
        bool nxt = (k0 + 16) < K;
        if (nxt) {
            ra0 = *(const uint4*)(aptr + k0 + 16);
            ra1 = *(const uint4*)(aptr + k0 + 24);
            rb0 = *(const uint4*)(bptr + k0 + 16);
            rb1 = *(const uint4*)(bptr + k0 + 24);
        }

        unsigned so = cur * STGB;
        unsigned bf[8][2];
#pragma unroll
        for (int ntp = 0; ntp < 4; ntp++)
            ldsm_x4(bf[2*ntp][0], bf[2*ntp][1], bf[2*ntp+1][0], bf[2*ntp+1][1],
                    bsBase + so + bLd + ntp * (16 * HSTR * 4));
#pragma unroll
        for (int mt = 0; mt < 4; mt++) {
            unsigned a0, a1, a2, a3;
            ldsm_x4(a0, a1, a2, a3, asBase + so + aLd + mt * (16 * HSTR * 4));
#pragma unroll
            for (int nt = 0; nt < 8; nt++)
                mma_h16(acc[mt][nt][0], acc[mt][nt][1], acc[mt][nt][2], acc[mt][nt][3],
                        a0, a1, a2, a3, bf[nt][0], bf[nt][1]);
        }

        if (nxt) {
            int s = cur ^ 1;
            *(uint4*)(As[s] + tid * HSTR)     = ra0;
            *(uint4*)(As[s] + tid * HSTR + 4) = ra1;
            *(uint4*)(Bs[s] + tid * HSTR)     = rb0;
            *(uint4*)(Bs[s] + tid * HSTR + 4) = rb1;
        }
        __syncthreads();
        cur ^= 1;
    }

#pragma unroll
    for (int mt = 0; mt < 4; mt++) {
#pragma unroll
        for (int nt = 0; nt < 8; nt++) {
            int row = m0 + wm * 64 + mt * 16 + g;
            int col = n0 + wn * 64 + nt * 8 + tig * 2;
            if (col < N) {
                *(float2*)(Cb + (long)row * ldc + col)       = make_float2(acc[mt][nt][0], acc[mt][nt][1]);
                *(float2*)(Cb + (long)(row + 8) * ldc + col) = make_float2(acc[mt][nt][2], acc[mt][nt][3]);
            }
        }
    }
}

// ------- causal conv1d(width 4) + bias + silu, 4 channels/thread; emits fp16 B|C -------
#define C4 (CDIM / 4)   // 1088
__global__ void k_conv(const float* __restrict__ zx, const float* __restrict__ w,
                       const float* __restrict__ bias, float* __restrict__ xbc,
                       __half* __restrict__ bch)
{
    int i = blockIdx.x * 256 + threadIdx.x;
    if (i >= TOK * C4) return;
    int t = i / C4, c4 = i - t * C4;
    int c = c4 * 4;
    int l = t & (SEQ - 1);

    float4 acc = *(const float4*)&bias[c];
    float4 w0 = *(const float4*)&w[(c + 0) * 4];
    float4 w1 = *(const float4*)&w[(c + 1) * 4];
    float4 w2 = *(const float4*)&w[(c + 2) * 4];
    float4 w3 = *(const float4*)&w[(c + 3) * 4];
    const float* base = zx + (long)t * DPROJ + DINNER + c;

#pragma unroll
    for (int k = 0; k < 4; k++) {
        int lt = l - 3 + k;
        if (lt >= 0) {
            float4 xv = *(const float4*)(base + (long)(k - 3) * DPROJ);
            float a0 = (k == 0) ? w0.x : (k == 1) ? w0.y : (k == 2) ? w0.z : w0.w;
            float a1 = (k == 0) ? w1.x : (k == 1) ? w1.y : (k == 2) ? w1.z : w1.w;
            float a2 = (k == 0) ? w2.x : (k == 1) ? w2.y : (k == 2) ? w2.z : w2.w;
            float a3 = (k == 0) ? w3.x : (k == 1) ? w3.y : (k == 2) ? w3.z : w3.w;
            acc.x = fmaf(a0, xv.x, acc.x);
            acc.y = fmaf(a1, xv.y, acc.y);
            acc.z = fmaf(a2, xv.z, acc.z);
            acc.w = fmaf(a3, xv.w, acc.w);
        }
    }
    float4 o;
    o.x = fsilu(acc.x); o.y = fsilu(acc.y); o.z = fsilu(acc.z); o.w = fsilu(acc.w);
    *(float4*)&xbc[(long)t * CDIM + c] = o;
    if (c >= DINNER) {
        *(uint2*)&bch[(long)t * (2 * NST) + (c - DINNER)] =
            make_uint2(f2h2(o.x, o.y), f2h2(o.z, o.w));
    }
}

// ------- per-(chunk,head) softplus(dt) + cumsum of dt*A (fused; writes dt too) -------
__global__ void k_dacs(const float* __restrict__ zx, const float* __restrict__ dt_bias,
                       const float* __restrict__ Alog, float* __restrict__ dtv,
                       float* __restrict__ dacs)
{
    int cc = blockIdx.x >> 6, h = blockIdx.x & 63;
    int s = threadIdx.x;
    int t = cc * CK + s;
    float raw = zx[(long)t * DPROJ + (DINNER + CDIM) + h] + dt_bias[h];
    float d = (raw > 20.f) ? raw : log1pf(expf(raw));
    dtv[t * NH + h] = d;
    float a = -expf(Alog[h]);
    float v = d * a;
    __shared__ float sm[CK];
    sm[s] = v; __syncthreads();
    for (int off = 1; off < CK; off <<= 1) {
        float tv = (s >= off) ? sm[s - off] : 0.f;
        __syncthreads();
        sm[s] += tv;
        __syncthreads();
    }
    dacs[(blockIdx.x << 8) + s] = sm[s];
}

// ======= chunk states via fp16 MMA =======
#define YSTR 36
__global__ __launch_bounds__(256) void k_states_mma(const float* __restrict__ xbc,
        const float* __restrict__ dt, const float* __restrict__ dacs, float* __restrict__ st)
{
    const int cc = blockIdx.x >> 6, h = blockIdx.x & 63;
    const int tb = cc * CK;
    const int tid = threadIdx.x, wid = tid >> 5, lane = tid & 31;
    const int g = lane >> 2, tig = lane & 3;
    const int wm = wid & 3, wn = wid >> 2;

    __shared__ unsigned At[64 * YSTR];
    __shared__ unsigned Bt[128 * YSTR];
    __shared__ float sdecay[CK];

    const float* dA = dacs + (blockIdx.x << 8);
    {
        float dlast = dA[CK - 1];
        sdecay[tid] = __expf(dlast - dA[tid]);
    }
    __syncthreads();

    float acc[8][4];
#pragma unroll
    for (int j = 0; j < 8; j++)
#pragma unroll
        for (int r = 0; r < 4; r++) acc[j][r] = 0.f;

    for (int s0 = 0; s0 < CK; s0 += 64) {
#pragma unroll
        for (int it = 0; it < 8; it++) {
            int idx = it * 256 + tid;
            int p = idx & 63, sq = idx >> 6;
            int t0 = tb + s0 + 2 * sq;
            float v0 = xbc[(long)t0 * CDIM + h * HD + p] * dt[t0 * NH + h];
            float v1 = xbc[(long)(t0 + 1) * CDIM + h * HD + p] * dt[(t0 + 1) * NH + h];
            At[p * YSTR + sq] = f2h2(v0, v1);
        }
#pragma unroll
        for (int it = 0; it < 16; it++) {
            int idx = it * 256 + tid;
            int n = idx & 127, sq = idx >> 7;
            int t0 = tb + s0 + 2 * sq;
            float v0 = xbc[(long)t0 * CDIM + DINNER + n] * sdecay[s0 + 2 * sq];
            float v1 = xbc[(long)(t0 + 1) * CDIM + DINNER + n] * sdecay[s0 + 2 * sq + 1];
            Bt[n * YSTR + sq] = f2h2(v0, v1);
        }
        __syncthreads();
#pragma unroll
        for (int ks = 0; ks < 4; ks++) {
            unsigned bf[8][2];
#pragma unroll
            for (int nt = 0; nt < 8; nt++) {
                const unsigned* bp = Bt + (wn * 64 + nt * 8 + g) * YSTR + ks * 8;
                bf[nt][0] = bp[tig]; bf[nt][1] = bp[tig + 4];
            }
            const unsigned* ap = At + (wm * 16 + g) * YSTR + ks * 8;
            unsigned a0 = ap[tig], a2 = ap[tig + 4];
            unsigned a1 = ap[8 * YSTR + tig], a3 = ap[8 * YSTR + tig + 4];
#pragma unroll
            for (int nt = 0; nt < 8; nt++)
                mma_h16(acc[nt][0], acc[nt][1], acc[nt][2], acc[nt][3],
                        a0, a1, a2, a3, bf[nt][0], bf[nt][1]);
        }
        __syncthreads();
    }

    float* ob = st + ((long)blockIdx.x << 13);
#pragma unroll
    for (int nt = 0; nt < 8; nt++) {
        int col = wn * 64 + nt * 8 + tig * 2;
        int row = wm * 16 + g;
        *(float2*)(ob + row * NST + col)       = make_float2(acc[nt][0], acc[nt][1]);
        *(float2*)(ob + (row + 8) * NST + col) = make_float2(acc[nt][2], acc[nt][3]);
    }
}

// ---------------- sequential chunk scan (4 quarter-blocks per (b,h)) ----------------
__global__ void k_scan(const float* __restrict__ st, const float* __restrict__ dacs,
                       float* __restrict__ pv)
{
    int bh = blockIdx.x >> 2, q = blockIdx.x & 3;
    int b = bh >> 6, h = bh & 63;
    int tid = threadIdx.x;
    int off = q * 2048 + tid;
    float carry[8];
#pragma unroll
    for (int j = 0; j < 8; j++) carry[j] = 0.f;
    for (int c = 0; c < 8; c++) {
        int cc = b * 8 + c;
        long base = (((long)(cc * 64 + h)) << 13) + off;
        float dec = __expf(dacs[((cc * 64 + h) << 8) + CK - 1]);
#pragma unroll
        for (int j = 0; j < 8; j++) {
            long e = base + j * 256;
            pv[e] = carry[j];
            carry[j] = carry[j] * dec + st[e];
        }
    }
}

// ======= k_y via fp16 MMA: Y = (W@xdt) + (C*el)@prev^T, + D*x, gated =======
__global__ __launch_bounds__(256) void k_y_mma(const float* __restrict__ xbc,
        const float* __restrict__ zx, const float* __restrict__ dt,
        const float* __restrict__ dacs, const float* __restrict__ cb,
        const float* __restrict__ pv, const float* __restrict__ Dsk,
        float* __restrict__ y)
{
    const int cc = blockIdx.x >> 6, h = blockIdx.x & 63;
    const int tb = cc * CK;
    const int tid = threadIdx.x, wid = tid >> 5, lane = tid & 31;
    const int g = lane >> 2, tig = lane & 3;

    __shared__ unsigned At[256 * YSTR];
    __shared__ unsigned Bt[64 * YSTR];
    __shared__ float sda[256];
    __shared__ float sel[256];

    sda[tid] = dacs[(blockIdx.x << 8) + tid];
    __syncthreads();
    sel[tid] = __expf(sda[(tid >> 6) << 6] - sda[tid]);
    __syncthreads();

    float acc[2][8][4];
#pragma unroll
    for (int i = 0; i < 2; i++)
#pragma unroll
        for (int j = 0; j < 8; j++)
#pragma unroll
            for (int r = 0; r < 4; r++) acc[i][j][r] = 0.f;

    const float* cbb = cb + ((long)cc << 16);

    // ---- phase 1: Y_diag, 4 s-tiles of 64 ----
    for (int st4 = 0; st4 < 4; st4++) {
        int s0 = st4 * 64;
        float Rt = sda[s0] - sda[s0 + 63];
        bool fast = (Rt <= 60.f);
        {
            int l = tid;
            unsigned* arow = At + l * YSTR;
            if (l < s0) {
#pragma unroll 8
                for (int it = 0; it < 32; it++) arow[it] = 0u;
            } else {
                float dal = sda[l];
                if (fast) {
                    float f1 = __expf(dal - sda[s0]);
#pragma unroll 4
                    for (int it = 0; it < 32; it++) {
                        int s = s0 + 2 * it;
                        float w0 = 0.f, w1 = 0.f;
                        if (s <= l) {
                            w0 = f1 * sel[s] * cbb[(s << 8) + l];
                            if (s + 1 <= l)
                                w1 = f1 * sel[s + 1] * cbb[((s + 1) << 8) + l];
                        }
                        arow[it] = f2h2(w0, w1);
                    }
                } else {
#pragma unroll 4
                    for (int it = 0; it < 32; it++) {
                        int s = s0 + 2 * it;
                        float w0 = 0.f, w1 = 0.f;
                        if (s <= l) {
                            w0 = __expf(dal - sda[s]) * cbb[(s << 8) + l];
                            if (s + 1 <= l)
                                w1 = __expf(dal - sda[s + 1]) * cbb[((s + 1) << 8) + l];
                        }
                        arow[it] = f2h2(w0, w1);
                    }
                }
            }
        }
#pragma unroll
        for (int it = 0; it < 8; it++) {
            int idx = it * 256 + tid;
            int p = idx & 63, sq = idx >> 6;
            int t0 = tb + s0 + 2 * sq;
            float v0 = xbc[(long)t0 * CDIM + h * HD + p] * dt[t0 * NH + h];
            float v1 = xbc[(long)(t0 + 1) * CDIM + h * HD + p] * dt[(t0 + 1) * NH + h];
            Bt[p * YSTR + sq] = f2h2(v0, v1);
        }
        __syncthreads();
        if (wid * 32 + 31 >= s0) {
#pragma unroll
            for (int ks = 0; ks < 4; ks++) {
                unsigned bf[8][2];
#pragma unroll
                for (int nt = 0; nt < 8; nt++) {
                    const unsigned* bp = Bt + (nt * 8 + g) * YSTR + ks * 8;
                    bf[nt][0] = bp[tig]; bf[nt][1] = bp[tig + 4];
                }
#pragma unroll
                for (int mt = 0; mt < 2; mt++) {
                    const unsigned* ap = At + (wid * 32 + mt * 16 + g) * YSTR + ks * 8;
                    unsigned a0 = ap[tig], a2 = ap[tig + 4];
                    unsigned a1 = ap[8 * YSTR + tig], a3 = ap[8 * YSTR + tig + 4];
#pragma unroll
                    for (int nt = 0; nt < 8; nt++)
                        mma_h16(acc[mt][nt][0], acc[mt][nt][1], acc[mt][nt][2], acc[mt][nt][3],
                                a0, a1, a2, a3, bf[nt][0], bf[nt][1]);
                }
            }
        }
        __syncthreads();
    }

    // phase-2 role of sel: exp(dA[l])
    sel[tid] = __expf(sda[tid]);
    __syncthreads();

    // ---- phase 2: Y_off, 2 n-subtiles of 64 ----
    const float* pvb = pv + ((long)blockIdx.x << 13);
    for (int ns = 0; ns < 2; ns++) {
        int n0 = ns * 64;
#pragma unroll
        for (int it = 0; it < 32; it++) {
            int idx = it * 256 + tid;
            int np = idx & 31, l = idx >> 5;
            float el = sel[l];
            float2 v = *(const float2*)&xbc[(long)(tb + l) * CDIM + DINNER + NST + n0 + 2 * np];
            At[l * YSTR + np] = f2h2(v.x * el, v.y * el);
        }
#pragma unroll
        for (int it = 0; it < 8; it++) {
            int idx = it * 256 + tid;
            int np = idx & 31, p = idx >> 5;
            float2 v = *(const float2*)&pvb[p * NST + n0 + 2 * np];
            Bt[p * YSTR + np] = f2h2(v.x, v.y);
        }
        __syncthreads();
#pragma unroll
        for (int ks = 0; ks < 4; ks++) {
            unsigned bf[8][2];
#pragma unroll
            for (int nt = 0; nt < 8; nt++) {
                const unsigned* bp = Bt + (nt * 8 + g) * YSTR + ks * 8;
                bf[nt][0] = bp[tig]; bf[nt][1] = bp[tig + 4];
            }
#pragma unroll
            for (int mt = 0; mt < 2; mt++) {
                const unsigned* ap = At + (wid * 32 + mt * 16 + g) * YSTR + ks * 8;
                unsigned a0 = ap[tig], a2 = ap[tig + 4];
                unsigned a1 = ap[8 * YSTR + tig], a3 = ap[8 * YSTR + tig + 4];
#pragma unroll
                for (int nt = 0; nt < 8; nt++)
                    mma_h16(acc[mt][nt][0], acc[mt][nt][1], acc[mt][nt][2], acc[mt][nt][3],
                            a0, a1, a2, a3, bf[nt][0], bf[nt][1]);
            }
        }
        __syncthreads();
    }

    // ---- epilogue: + D*x, gate silu(z) ----
    float dsk = Dsk[h];
#pragma unroll
    for (int mt = 0; mt < 2; mt++) {
#pragma unroll
        for (int nt = 0; nt < 8; nt++) {
            int col = nt * 8 + tig * 2;
#pragma unroll
            for (int rr = 0; rr < 2; rr++) {
                int l = wid * 32 + mt * 16 + g + rr * 8;
                int t = tb + l;
                float2 xv = *(const float2*)&xbc[(long)t * CDIM + h * HD + col];
                float2 zv = *(const float2*)&zx[(long)t * DPROJ + h * HD + col];
                float o0 = (acc[mt][nt][rr * 2 + 0] + xv.x * dsk) * fsilu(zv.x);
                float o1 = (acc[mt][nt][rr * 2 + 1] + xv.y * dsk) * fsilu(zv.y);
                *(float2*)&y[(long)t * DINNER + h * HD + col] = make_float2(o0, o1);
            }
        }
    }
}

// ---------------- RMSNorm: reads y fp32, writes normalized fp16 ----------------
__global__ void k_rms(const float* __restrict__ y, const float* __restrict__ nw,
                      __half* __restrict__ yh)
{
    int t = blockIdx.x;
    const float4* row = (const float4*)(y + (long)t * DINNER);
    const float4* nw4 = (const float4*)nw;
    float ss = 0.f;
    for (int i = threadIdx.x; i < DINNER / 4; i += 256) {
        float4 v = row[i];
        ss = fmaf(v.x, v.x, ss); ss = fmaf(v.y, v.y, ss);
        ss = fmaf(v.z, v.z, ss); ss = fmaf(v.w, v.w, ss);
    }
    __shared__ float red[256];
    red[threadIdx.x] = ss; __syncthreads();
    for (int o = 128; o > 0; o >>= 1) {
        if (threadIdx.x < o) red[threadIdx.x] += red[threadIdx.x + o];
        __syncthreads();
    }
    float sc = rsqrtf(red[0] / (float)DINNER + 1e-5f);
    uint2* oh = (uint2*)(yh + (long)t * DINNER);
    for (int i = threadIdx.x; i < DINNER / 4; i += 256) {
        float4 v = row[i], n = nw4[i];
        oh[i] = make_uint2(f2h2(v.x * sc * n.x, v.y * sc * n.y),
                           f2h2(v.z * sc * n.z, v.w * sc * n.w));
    }
}

// ---------------- launch ----------------
extern "C" void kernel_launch(void* const* d_in, const int* in_sizes, int n_in,
                              void* d_out, int out_size)
{
    const float* u     = (const float*)d_in[0];
    const float* Win   = (const float*)d_in[1];
    const float* convw = (const float*)d_in[2];
    const float* convb = (const float*)d_in[3];
    const float* dtb   = (const float*)d_in[4];
    const float* Alog  = (const float*)d_in[5];
    const float* Dsk   = (const float*)d_in[6];
    const float* nw    = (const float*)d_in[7];
    const float* Wout  = (const float*)d_in[8];
    float* out = (float*)d_out;

    static float *zx = nullptr, *xbc, *dt, *dacs, *cb, *st, *pv, *y;
    static __half *uh, *winh, *wouth, *bch, *yh;
    if (!zx) {
        cudaGetSymbolAddress((void**)&xbc,   g_xbc);
        cudaGetSymbolAddress((void**)&dt,    g_dtv);
        cudaGetSymbolAddress((void**)&dacs,  g_dacs);
        cudaGetSymbolAddress((void**)&cb,    g_cb);
        cudaGetSymbolAddress((void**)&st,    g_st);
        cudaGetSymbolAddress((void**)&pv,    g_pv);
        cudaGetSymbolAddress((void**)&y,     g_y);
        cudaGetSymbolAddress((void**)&uh,    g_uh);
        cudaGetSymbolAddress((void**)&winh,  g_winh);
        cudaGetSymbolAddress((void**)&wouth, g_wouth);
        cudaGetSymbolAddress((void**)&bch,   g_bch);
        cudaGetSymbolAddress((void**)&yh,    g_yh);
        cudaGetSymbolAddress((void**)&zx,    g_zx);
    }

    // 0) fp16 conversions of GEMM operands
    k_cvt<<<(TOK * DMODEL / 4 + 255) / 256, 256>>>(u, uh, TOK * DMODEL / 4);
    k_cvt<<<(DPROJ * DMODEL / 4 + 255) / 256, 256>>>(Win, winh, DPROJ * DMODEL / 4);
    k_cvt<<<(DMODEL * DINNER / 4 + 255) / 256, 256>>>(Wout, wouth, DMODEL * DINNER / 4);

    // 1) in_proj: zx = u @ Win^T   (M=4096, N=8512, K=2048)
    gemm_h16n<<<dim3((DPROJ + 127) / 128, TOK / 128, 1), 128>>>(uh, winh, zx,
        DMODEL, DMODEL, DMODEL, DPROJ, DPROJ, 0, 0, 0);

    // 2) conv + silu (4 channels/thread, emits fp16 B|C slice)
    k_conv<<<(TOK * C4 + 255) / 256, 256>>>(zx, convw, convb, xbc, bch);

    // 3) softplus(dt) + dA cumsum (fused)
    k_dacs<<<NCC * NH, CK>>>(zx, dtb, Alog, dt, dacs);

    // 4) CB^T[cc][s][l] = B[s]·C[l]   (batched, fp16-native; M=256,N=256,K=128)
    gemm_h16n<<<dim3(CK / 128, CK / 128, NCC), 128>>>(bch, bch + NST, cb,
        NST, 2 * NST, 2 * NST, CK, CK, (long)CK * 2 * NST, (long)CK * 2 * NST, (long)CK * CK);

    // 5) chunk states (tensor-core)
    k_states_mma<<<NCC * NH, 256>>>(xbc, dt, dacs, st);

    // 6) inter-chunk scan (4x parallelism)
    k_scan<<<2 * NH * 4, 256>>>(st, dacs, pv);

    // 7) Y = Y_diag + Y_off + skip, gated  (tensor-core)
    k_y_mma<<<NCC * NH, 256>>>(xbc, zx, dt, dacs, cb, pv, Dsk, y);

    // 8) RMSNorm -> fp16
    k_rms<<<TOK, 256>>>(y, nw, yh);

    // 9) out_proj: out = yh @ Wout^T  (M=4096, N=2048, K=4096)
    gemm_h16n<<<dim3(DMODEL / 128, TOK / 128, 1), 128>>>(yh, wouth, out,
        DINNER, DINNER, DINNER, DMODEL, DMODEL, 0, 0, 0);
}

// round 17
// speedup vs baseline: 1.0918x; 1.0918x over previous
#include <cuda_runtime.h>
#include <cuda_fp16.h>

// ---------------- problem constants ----------------
#define TOK    4096        // BATCH*SEQLEN
#define DMODEL 2048
#define DINNER 4096
#define NH     64
#define HD     64
#define NST    128
#define CDIM   4352        // DINNER + 2*NST
#define DPROJ  8512        // 2*DINNER + 2*NST + NH
#define SEQ    2048
#define CK     256         // chunk length
#define NCC    16          // BATCH * (SEQ/CK) total chunks

// ---------------- scratch (device globals; no allocation) ----------------
__device__ __align__(16) float  g_zx  [(size_t)TOK*DPROJ];
__device__ __align__(16) float  g_xbc [(size_t)TOK*CDIM];
__device__ __align__(16) float  g_dtv [(size_t)TOK*NH];
__device__ __align__(16) float  g_dacs[(size_t)NCC*NH*CK];
__device__ __align__(16) float  g_cb  [(size_t)NCC*CK*CK];
__device__ __align__(16) float  g_st  [(size_t)NCC*NH*HD*NST];
__device__ __align__(16) float  g_pv  [(size_t)NCC*NH*HD*NST];
__device__ __align__(16) float  g_y   [(size_t)TOK*DINNER];
__device__ __align__(16) __half g_uh  [(size_t)TOK*DMODEL];
__device__ __align__(16) __half g_winh[(size_t)DPROJ*DMODEL];
__device__ __align__(16) __half g_wouth[(size_t)DMODEL*DINNER];
__device__ __align__(16) __half g_bch [(size_t)TOK*2*NST];
__device__ __align__(16) __half g_yh  [(size_t)TOK*DINNER];

// ---------------- helpers ----------------
__device__ __forceinline__ unsigned f2h2(float lo, float hi) {
    __half2 h = __floats2half2_rn(lo, hi);
    return *(unsigned*)&h;
}
__device__ __forceinline__ void mma_h16(float& c0, float& c1, float& c2, float& c3,
                                        unsigned a0, unsigned a1, unsigned a2, unsigned a3,
                                        unsigned b0, unsigned b1) {
    asm volatile("mma.sync.aligned.m16n8k16.row.col.f32.f16.f16.f32 "
                 "{%0,%1,%2,%3}, {%4,%5,%6,%7}, {%8,%9}, {%0,%1,%2,%3};"
                 : "+f"(c0), "+f"(c1), "+f"(c2), "+f"(c3)
                 : "r"(a0), "r"(a1), "r"(a2), "r"(a3), "r"(b0), "r"(b1));
}
__device__ __forceinline__ void ldsm_x4(unsigned& r0, unsigned& r1, unsigned& r2,
                                        unsigned& r3, unsigned addr) {
    asm volatile("ldmatrix.sync.aligned.m8n8.x4.shared.b16 {%0,%1,%2,%3}, [%4];"
                 : "=r"(r0), "=r"(r1), "=r"(r2), "=r"(r3) : "r"(addr));
}
__device__ __forceinline__ float fsilu(float v) {
    return v * __fdividef(1.f, 1.f + __expf(-v));
}

// ---------------- fp32 -> fp16 convert (vectorized) ----------------
__global__ void k_cvt(const float* __restrict__ in, __half* __restrict__ out, int n4)
{
    int i = blockIdx.x * 256 + threadIdx.x;
    if (i >= n4) return;
    float4 v = ((const float4*)in)[i];
    ((uint2*)out)[i] = make_uint2(f2h2(v.x, v.y), f2h2(v.z, v.w));
}

// ------- fp16-NATIVE GEMM, ldmatrix frags (R15 proven config) -------
// BM=128, BN=128, BK=16, 256 thr (8 warps), warp tile 32x64, DOUBLE-BUFFERED.
#define HSTR 12
__global__ __launch_bounds__(256) void gemm_h16n(
    const __half* __restrict__ A, const __half* __restrict__ B, float* __restrict__ C,
    int K, int lda, int ldb, int ldc, int N, long aB, long bB, long cB)
{
    const __half* Ab = A + (long)blockIdx.z * aB;
    const __half* Bb = B + (long)blockIdx.z * bB;
    float*        Cb = C + (long)blockIdx.z * cB;

    __shared__ unsigned As[2][128 * HSTR];
    __shared__ unsigned Bs[2][128 * HSTR];

    int tid  = threadIdx.x;
    int wid  = tid >> 5, lane = tid & 31;
    int g    = lane >> 2, tig = lane & 3;
    int wm   = wid & 3, wn = wid >> 2;          // 4 m-warps x 2 n-warps; warp tile 32x64
    int m0   = blockIdx.y * 128, n0 = blockIdx.x * 128;

    int aRow = tid >> 1, aColH = (tid & 1) * 8;
    const __half* aptr = Ab + (long)(m0 + aRow) * lda + aColH;
    int bR = n0 + aRow; if (bR >= N) bR = N - 1;
    const __half* bptr = Bb + (long)bR * ldb + aColH;

    unsigned asBase = (unsigned)__cvta_generic_to_shared(&As[0][0]);
    unsigned bsBase = (unsigned)__cvta_generic_to_shared(&Bs[0][0]);
    unsigned aLd = ((unsigned)((wm * 32 + ((lane >> 3) & 1) * 8 + (lane & 7)) * HSTR
                               + (lane >> 4) * 4)) * 4u;
    unsigned bLd = ((unsigned)((wn * 64 + ((lane >> 4) & 1) * 8 + (lane & 7)) * HSTR
                               + ((lane >> 3) & 1) * 4)) * 4u;
    const unsigned STGB = 128 * HSTR * 4;

    float acc[2][8][4];
#pragma unroll
    for (int i = 0; i < 2; i++)
#pragma unroll
        for (int j = 0; j < 8; j++)
#pragma unroll
            for (int r = 0; r < 4; r++) acc[i][j][r] = 0.f;

    uint4 ra = *(const uint4*)(aptr);
    uint4 rb = *(const uint4*)(bptr);
    *(uint4*)(As[0] + aRow * HSTR + (tid & 1) * 4) = ra;
    *(uint4*)(Bs[0] + aRow * HSTR + (tid & 1) * 4) = rb;
    __syncthreads();

    int cur = 0;
    for (int k0 = 0; k0 < K; k0 += 16) {
        bool nxt = (k0 + 16) < K;
        if (nxt) {
            ra = *(const uint4*)(aptr + k0 + 16);
            rb = *(const uint4*)(bptr + k0 + 16);
        }

        unsigned so = cur * STGB;
        unsigned bf[8][2];
#pragma unroll
        for (int ntp = 0; ntp < 4; ntp++)
            ldsm_x4(bf[2*ntp][0], bf[2*ntp][1], bf[2*ntp+1][0], bf[2*ntp+1][1],
                    bsBase + so + bLd + ntp * (16 * HSTR * 4));
#pragma unroll
        for (int mt = 0; mt < 2; mt++) {
            unsigned a0, a1, a2, a3;
            ldsm_x4(a0, a1, a2, a3, asBase + so + aLd + mt * (16 * HSTR * 4));
#pragma unroll
            for (int nt = 0; nt < 8; nt++)
                mma_h16(acc[mt][nt][0], acc[mt][nt][1], acc[mt][nt][2], acc[mt][nt][3],
                        a0, a1, a2, a3, bf[nt][0], bf[nt][1]);
        }

        if (nxt) {
            int s = cur ^ 1;
            *(uint4*)(As[s] + aRow * HSTR + (tid & 1) * 4) = ra;
            *(uint4*)(Bs[s] + aRow * HSTR + (tid & 1) * 4) = rb;
        }
        __syncthreads();
        cur ^= 1;
    }

#pragma unroll
    for (int mt = 0; mt < 2; mt++) {
#pragma unroll
        for (int nt = 0; nt < 8; nt++) {
            int row = m0 + wm * 32 + mt * 16 + g;
            int col = n0 + wn * 64 + nt * 8 + tig * 2;
            if (col < N) {
                *(float2*)(Cb + (long)row * ldc + col)       = make_float2(acc[mt][nt][0], acc[mt][nt][1]);
                *(float2*)(Cb + (long)(row + 8) * ldc + col) = make_float2(acc[mt][nt][2], acc[mt][nt][3]);
            }
        }
    }
}

// ------- causal conv1d(width 4) + bias + silu, 4 channels/thread; emits fp16 B|C -------
#define C4 (CDIM / 4)   // 1088
__global__ void k_conv(const float* __restrict__ zx, const float* __restrict__ w,
                       const float* __restrict__ bias, float* __restrict__ xbc,
                       __half* __restrict__ bch)
{
    int i = blockIdx.x * 256 + threadIdx.x;
    if (i >= TOK * C4) return;
    int t = i / C4, c4 = i - t * C4;
    int c = c4 * 4;
    int l = t & (SEQ - 1);

    float4 acc = *(const float4*)&bias[c];
    float4 w0 = *(const float4*)&w[(c + 0) * 4];
    float4 w1 = *(const float4*)&w[(c + 1) * 4];
    float4 w2 = *(const float4*)&w[(c + 2) * 4];
    float4 w3 = *(const float4*)&w[(c + 3) * 4];
    const float* base = zx + (long)t * DPROJ + DINNER + c;

#pragma unroll
    for (int k = 0; k < 4; k++) {
        int lt = l - 3 + k;
        if (lt >= 0) {
            float4 xv = *(const float4*)(base + (long)(k - 3) * DPROJ);
            float a0 = (k == 0) ? w0.x : (k == 1) ? w0.y : (k == 2) ? w0.z : w0.w;
            float a1 = (k == 0) ? w1.x : (k == 1) ? w1.y : (k == 2) ? w1.z : w1.w;
            float a2 = (k == 0) ? w2.x : (k == 1) ? w2.y : (k == 2) ? w2.z : w2.w;
            float a3 = (k == 0) ? w3.x : (k == 1) ? w3.y : (k == 2) ? w3.z : w3.w;
            acc.x = fmaf(a0, xv.x, acc.x);
            acc.y = fmaf(a1, xv.y, acc.y);
            acc.z = fmaf(a2, xv.z, acc.z);
            acc.w = fmaf(a3, xv.w, acc.w);
        }
    }
    float4 o;
    o.x = fsilu(acc.x); o.y = fsilu(acc.y); o.z = fsilu(acc.z); o.w = fsilu(acc.w);
    *(float4*)&xbc[(long)t * CDIM + c] = o;
    if (c >= DINNER) {
        *(uint2*)&bch[(long)t * (2 * NST) + (c - DINNER)] =
            make_uint2(f2h2(o.x, o.y), f2h2(o.z, o.w));
    }
}

// ------- per-(chunk,head) softplus(dt) + cumsum of dt*A (fused; writes dt too) -------
__global__ void k_dacs(const float* __restrict__ zx, const float* __restrict__ dt_bias,
                       const float* __restrict__ Alog, float* __restrict__ dtv,
                       float* __restrict__ dacs)
{
    int cc = blockIdx.x >> 6, h = blockIdx.x & 63;
    int s = threadIdx.x;
    int t = cc * CK + s;
    float raw = zx[(long)t * DPROJ + (DINNER + CDIM) + h] + dt_bias[h];
    float d = (raw > 20.f) ? raw : log1pf(expf(raw));
    dtv[t * NH + h] = d;
    float a = -expf(Alog[h]);
    float v = d * a;
    __shared__ float sm[CK];
    sm[s] = v; __syncthreads();
    for (int off = 1; off < CK; off <<= 1) {
        float tv = (s >= off) ? sm[s - off] : 0.f;
        __syncthreads();
        sm[s] += tv;
        __syncthreads();
    }
    dacs[(blockIdx.x << 8) + s] = sm[s];
}

// ======= chunk states via fp16 MMA (LDSM fragment loads) =======
#define YSTR 36
__global__ __launch_bounds__(256) void k_states_mma(const float* __restrict__ xbc,
        const float* __restrict__ dt, const float* __restrict__ dacs, float* __restrict__ st)
{
    const int cc = blockIdx.x >> 6, h = blockIdx.x & 63;
    const int tb = cc * CK;
    const int tid = threadIdx.x, wid = tid >> 5, lane = tid & 31;
    const int g = lane >> 2, tig = lane & 3;
    const int wm = wid & 3, wn = wid >> 2;

    __shared__ unsigned At[64 * YSTR];
    __shared__ unsigned Bt[128 * YSTR];
    __shared__ float sdecay[CK];

    unsigned atB = (unsigned)__cvta_generic_to_shared(&At[0]);
    unsigned btB = (unsigned)__cvta_generic_to_shared(&Bt[0]);
    // A frag: rows wm*16 + lane-structured, k-half by lane>>4
    unsigned aLd = ((unsigned)((wm * 16 + ((lane >> 3) & 1) * 8 + (lane & 7)) * YSTR
                               + (lane >> 4) * 4)) * 4u;
    // B frag: 2 n-tiles per ldsm
    unsigned bLd = ((unsigned)((wn * 64 + ((lane >> 4) & 1) * 8 + (lane & 7)) * YSTR
                               + ((lane >> 3) & 1) * 4)) * 4u;

    const float* dA = dacs + (blockIdx.x << 8);
    {
        float dlast = dA[CK - 1];
        sdecay[tid] = __expf(dlast - dA[tid]);
    }
    __syncthreads();

    float acc[8][4];
#pragma unroll
    for (int j = 0; j < 8; j++)
#pragma unroll
        for (int r = 0; r < 4; r++) acc[j][r] = 0.f;

    for (int s0 = 0; s0 < CK; s0 += 64) {
#pragma unroll
        for (int it = 0; it < 8; it++) {
            int idx = it * 256 + tid;
            int p = idx & 63, sq = idx >> 6;
            int t0 = tb + s0 + 2 * sq;
            float v0 = xbc[(long)t0 * CDIM + h * HD + p] * dt[t0 * NH + h];
            float v1 = xbc[(long)(t0 + 1) * CDIM + h * HD + p] * dt[(t0 + 1) * NH + h];
            At[p * YSTR + sq] = f2h2(v0, v1);
        }
#pragma unroll
        for (int it = 0; it < 16; it++) {
            int idx = it * 256 + tid;
            int n = idx & 127, sq = idx >> 7;
            int t0 = tb + s0 + 2 * sq;
            float v0 = xbc[(long)t0 * CDIM + DINNER + n] * sdecay[s0 + 2 * sq];
            float v1 = xbc[(long)(t0 + 1) * CDIM + DINNER + n] * sdecay[s0 + 2 * sq + 1];
            Bt[n * YSTR + sq] = f2h2(v0, v1);
        }
        __syncthreads();
#pragma unroll
        for (int ks = 0; ks < 4; ks++) {
            unsigned bf[8][2];
#pragma unroll
            for (int ntp = 0; ntp < 4; ntp++)
                ldsm_x4(bf[2*ntp][0], bf[2*ntp][1], bf[2*ntp+1][0], bf[2*ntp+1][1],
                        btB + bLd + ntp * (16 * YSTR * 4) + ks * 32);
            unsigned a0, a1, a2, a3;
            ldsm_x4(a0, a1, a2, a3, atB + aLd + ks * 32);
#pragma unroll
            for (int nt = 0; nt < 8; nt++)
                mma_h16(acc[nt][0], acc[nt][1], acc[nt][2], acc[nt][3],
                        a0, a1, a2, a3, bf[nt][0], bf[nt][1]);
        }
        __syncthreads();
    }

    float* ob = st + ((long)blockIdx.x << 13);
#pragma unroll
    for (int nt = 0; nt < 8; nt++) {
        int col = wn * 64 + nt * 8 + tig * 2;
        int row = wm * 16 + g;
        *(float2*)(ob + row * NST + col)       = make_float2(acc[nt][0], acc[nt][1]);
        *(float2*)(ob + (row + 8) * NST + col) = make_float2(acc[nt][2], acc[nt][3]);
    }
}

// ---------------- sequential chunk scan (4 quarter-blocks per (b,h)) ----------------
__global__ void k_scan(const float* __restrict__ st, const float* __restrict__ dacs,
                       float* __restrict__ pv)
{
    int bh = blockIdx.x >> 2, q = blockIdx.x & 3;
    int b = bh >> 6, h = bh & 63;
    int tid = threadIdx.x;
    int off = q * 2048 + tid;
    float carry[8];
#pragma unroll
    for (int j = 0; j < 8; j++) carry[j] = 0.f;
    for (int c = 0; c < 8; c++) {
        int cc = b * 8 + c;
        long base = (((long)(cc * 64 + h)) << 13) + off;
        float dec = __expf(dacs[((cc * 64 + h) << 8) + CK - 1]);
#pragma unroll
        for (int j = 0; j < 8; j++) {
            long e = base + j * 256;
            pv[e] = carry[j];
            carry[j] = carry[j] * dec + st[e];
        }
    }
}

// ======= k_y via fp16 MMA (LDSM fragment loads) =======
__global__ __launch_bounds__(256) void k_y_mma(const float* __restrict__ xbc,
        const float* __restrict__ zx, const float* __restrict__ dt,
        const float* __restrict__ dacs, const float* __restrict__ cb,
        const float* __restrict__ pv, const float* __restrict__ Dsk,
        float* __restrict__ y)
{
    const int cc = blockIdx.x >> 6, h = blockIdx.x & 63;
    const int tb = cc * CK;
    const int tid = threadIdx.x, wid = tid >> 5, lane = tid & 31;
    const int g = lane >> 2, tig = lane & 3;

    __shared__ unsigned At[256 * YSTR];
    __shared__ unsigned Bt[64 * YSTR];
    __shared__ float sda[256];
    __shared__ float sel[256];

    unsigned atB = (unsigned)__cvta_generic_to_shared(&At[0]);
    unsigned btB = (unsigned)__cvta_generic_to_shared(&Bt[0]);
    unsigned aLd = ((unsigned)((wid * 32 + ((lane >> 3) & 1) * 8 + (lane & 7)) * YSTR
                               + (lane >> 4) * 4)) * 4u;
    unsigned bLd = ((unsigned)((((lane >> 4) & 1) * 8 + (lane & 7)) * YSTR
                               + ((lane >> 3) & 1) * 4)) * 4u;

    sda[tid] = dacs[(blockIdx.x << 8) + tid];
    __syncthreads();
    sel[tid] = __expf(sda[(tid >> 6) << 6] - sda[tid]);
    __syncthreads();

    float acc[2][8][4];
#pragma unroll
    for (int i = 0; i < 2; i++)
#pragma unroll
        for (int j = 0; j < 8; j++)
#pragma unroll
            for (int r = 0; r < 4; r++) acc[i][j][r] = 0.f;

    const float* cbb = cb + ((long)cc << 16);

    // ---- phase 1: Y_diag, 4 s-tiles of 64 ----
    for (int st4 = 0; st4 < 4; st4++) {
        int s0 = st4 * 64;
        float Rt = sda[s0] - sda[s0 + 63];
        bool fast = (Rt <= 60.f);
        {
            int l = tid;
            unsigned* arow = At + l * YSTR;
            if (l < s0) {
#pragma unroll 8
                for (int it = 0; it < 32; it++) arow[it] = 0u;
            } else {
                float dal = sda[l];
                if (fast) {
                    float f1 = __expf(dal - sda[s0]);
#pragma unroll 4
                    for (int it = 0; it < 32; it++) {
                        int s = s0 + 2 * it;
                        float w0 = 0.f, w1 = 0.f;
                        if (s <= l) {
                            w0 = f1 * sel[s] * cbb[(s << 8) + l];
                            if (s + 1 <= l)
                                w1 = f1 * sel[s + 1] * cbb[((s + 1) << 8) + l];
                        }
                        arow[it] = f2h2(w0, w1);
                    }
                } else {
#pragma unroll 4
                    for (int it = 0; it < 32; it++) {
                        int s = s0 + 2 * it;
                        float w0 = 0.f, w1 = 0.f;
                        if (s <= l) {
                            w0 = __expf(dal - sda[s]) * cbb[(s << 8) + l];
                            if (s + 1 <= l)
                                w1 = __expf(dal - sda[s + 1]) * cbb[((s + 1) << 8) + l];
                        }
                        arow[it] = f2h2(w0, w1);
                    }
                }
            }
        }
#pragma unroll
        for (int it = 0; it < 8; it++) {
            int idx = it * 256 + tid;
            int p = idx & 63, sq = idx >> 6;
            int t0 = tb + s0 + 2 * sq;
            float v0 = xbc[(long)t0 * CDIM + h * HD + p] * dt[t0 * NH + h];
            float v1 = xbc[(long)(t0 + 1) * CDIM + h * HD + p] * dt[(t0 + 1) * NH + h];
            Bt[p * YSTR + sq] = f2h2(v0, v1);
        }
        __syncthreads();
        if (wid * 32 + 31 >= s0) {
#pragma unroll
            for (int ks = 0; ks < 4; ks++) {
                unsigned bf[8][2];
#pragma unroll
                for (int ntp = 0; ntp < 4; ntp++)
                    ldsm_x4(bf[2*ntp][0], bf[2*ntp][1], bf[2*ntp+1][0], bf[2*ntp+1][1],
                            btB + bLd + ntp * (16 * YSTR * 4) + ks * 32);
#pragma unroll
                for (int mt = 0; mt < 2; mt++) {
                    unsigned a0, a1, a2, a3;
                    ldsm_x4(a0, a1, a2, a3, atB + aLd + mt * (16 * YSTR * 4) + ks * 32);
#pragma unroll
                    for (int nt = 0; nt < 8; nt++)
                        mma_h16(acc[mt][nt][0], acc[mt][nt][1], acc[mt][nt][2], acc[mt][nt][3],
                                a0, a1, a2, a3, bf[nt][0], bf[nt][1]);
                }
            }
        }
        __syncthreads();
    }

    // phase-2 role of sel: exp(dA[l])
    sel[tid] = __expf(sda[tid]);
    __syncthreads();

    // ---- phase 2: Y_off, 2 n-subtiles of 64 ----
    const float* pvb = pv + ((long)blockIdx.x << 13);
    for (int ns = 0; ns < 2; ns++) {
        int n0 = ns * 64;
#pragma unroll
        for (int it = 0; it < 32; it++) {
            int idx = it * 256 + tid;
            int np = idx & 31, l = idx >> 5;
            float el = sel[l];
            float2 v = *(const float2*)&xbc[(long)(tb + l) * CDIM + DINNER + NST + n0 + 2 * np];
            At[l * YSTR + np] = f2h2(v.x * el, v.y * el);
        }
#pragma unroll
        for (int it = 0; it < 8; it++) {
            int idx = it * 256 + tid;
            int np = idx & 31, p = idx >> 5;
            float2 v = *(const float2*)&pvb[p * NST + n0 + 2 * np];
            Bt[p * YSTR + np] = f2h2(v.x, v.y);
        }
        __syncthreads();
#pragma unroll
        for (int ks = 0; ks < 4; ks++) {
            unsigned bf[8][2];
#pragma unroll
            for (int ntp = 0; ntp < 4; ntp++)
                ldsm_x4(bf[2*ntp][0], bf[2*ntp][1], bf[2*ntp+1][0], bf[2*ntp+1][1],
                        btB + bLd + ntp * (16 * YSTR * 4) + ks * 32);
#pragma unroll
            for (int mt = 0; mt < 2; mt++) {
                unsigned a0, a1, a2, a3;
                ldsm_x4(a0, a1, a2, a3, atB + aLd + mt * (16 * YSTR * 4) + ks * 32);
#pragma unroll
                for (int nt = 0; nt < 8; nt++)
                    mma_h16(acc[mt][nt][0], acc[mt][nt][1], acc[mt][nt][2], acc[mt][nt][3],
                            a0, a1, a2, a3, bf[nt][0], bf[nt][1]);
            }
        }
        __syncthreads();
    }

    // ---- epilogue: + D*x, gate silu(z) ----
    float dsk = Dsk[h];
#pragma unroll
    for (int mt = 0; mt < 2; mt++) {
#pragma unroll
        for (int nt = 0; nt < 8; nt++) {
            int col = nt * 8 + tig * 2;
#pragma unroll
            for (int rr = 0; rr < 2; rr++) {
                int l = wid * 32 + mt * 16 + g + rr * 8;
                int t = tb + l;
                float2 xv = *(const float2*)&xbc[(long)t * CDIM + h * HD + col];
                float2 zv = *(const float2*)&zx[(long)t * DPROJ + h * HD + col];
                float o0 = (acc[mt][nt][rr * 2 + 0] + xv.x * dsk) * fsilu(zv.x);
                float o1 = (acc[mt][nt][rr * 2 + 1] + xv.y * dsk) * fsilu(zv.y);
                *(float2*)&y[(long)t * DINNER + h * HD + col] = make_float2(o0, o1);
            }
        }
    }
}

// ---------------- RMSNorm: reads y fp32, writes normalized fp16 ----------------
__global__ void k_rms(const float* __restrict__ y, const float* __restrict__ nw,
                      __half* __restrict__ yh)
{
    int t = blockIdx.x;
    const float4* row = (const float4*)(y + (long)t * DINNER);
    const float4* nw4 = (const float4*)nw;
    float ss = 0.f;
    for (int i = threadIdx.x; i < DINNER / 4; i += 256) {
        float4 v = row[i];
        ss = fmaf(v.x, v.x, ss); ss = fmaf(v.y, v.y, ss);
        ss = fmaf(v.z, v.z, ss); ss = fmaf(v.w, v.w, ss);
    }
    __shared__ float red[256];
    red[threadIdx.x] = ss; __syncthreads();
    for (int o = 128; o > 0; o >>= 1) {
        if (threadIdx.x < o) red[threadIdx.x] += red[threadIdx.x + o];
        __syncthreads();
    }
    float sc = rsqrtf(red[0] / (float)DINNER + 1e-5f);
    uint2* oh = (uint2*)(yh + (long)t * DINNER);
    for (int i = threadIdx.x; i < DINNER / 4; i += 256) {
        float4 v = row[i], n = nw4[i];
        oh[i] = make_uint2(f2h2(v.x * sc * n.x, v.y * sc * n.y),
                           f2h2(v.z * sc * n.z, v.w * sc * n.w));
    }
}

// ---------------- launch ----------------
extern "C" void kernel_launch(void* const* d_in, const int* in_sizes, int n_in,
                              void* d_out, int out_size)
{
    const float* u     = (const float*)d_in[0];
    const float* Win   = (const float*)d_in[1];
    const float* convw = (const float*)d_in[2];
    const float* convb = (const float*)d_in[3];
    const float* dtb   = (const float*)d_in[4];
    const float* Alog  = (const float*)d_in[5];
    const float* Dsk   = (const float*)d_in[6];
    const float* nw    = (const float*)d_in[7];
    const float* Wout  = (const float*)d_in[8];
    float* out = (float*)d_out;

    static float *zx = nullptr, *xbc, *dt, *dacs, *cb, *st, *pv, *y;
    static __half *uh, *winh, *wouth, *bch, *yh;
    if (!zx) {
        cudaGetSymbolAddress((void**)&xbc,   g_xbc);
        cudaGetSymbolAddress((void**)&dt,    g_dtv);
        cudaGetSymbolAddress((void**)&dacs,  g_dacs);
        cudaGetSymbolAddress((void**)&cb,    g_cb);
        cudaGetSymbolAddress((void**)&st,    g_st);
        cudaGetSymbolAddress((void**)&pv,    g_pv);
        cudaGetSymbolAddress((void**)&y,     g_y);
        cudaGetSymbolAddress((void**)&uh,    g_uh);
        cudaGetSymbolAddress((void**)&winh,  g_winh);
        cudaGetSymbolAddress((void**)&wouth, g_wouth);
        cudaGetSymbolAddress((void**)&bch,   g_bch);
        cudaGetSymbolAddress((void**)&yh,    g_yh);
        cudaGetSymbolAddress((void**)&zx,    g_zx);
    }

    // 0) fp16 conversions of GEMM operands
    k_cvt<<<(TOK * DMODEL / 4 + 255) / 256, 256>>>(u, uh, TOK * DMODEL / 4);
    k_cvt<<<(DPROJ * DMODEL / 4 + 255) / 256, 256>>>(Win, winh, DPROJ * DMODEL / 4);
    k_cvt<<<(DMODEL * DINNER / 4 + 255) / 256, 256>>>(Wout, wouth, DMODEL * DINNER / 4);

    // 1) in_proj: zx = u @ Win^T   (M=4096, N=8512, K=2048)
    gemm_h16n<<<dim3((DPROJ + 127) / 128, TOK / 128, 1), 256>>>(uh, winh, zx,
        DMODEL, DMODEL, DMODEL, DPROJ, DPROJ, 0, 0, 0);

    // 2) conv + silu (4 channels/thread, emits fp16 B|C slice)
    k_conv<<<(TOK * C4 + 255) / 256, 256>>>(zx, convw, convb, xbc, bch);

    // 3) softplus(dt) + dA cumsum (fused)
    k_dacs<<<NCC * NH, CK>>>(zx, dtb, Alog, dt, dacs);

    // 4) CB^T[cc][s][l] = B[s]·C[l]   (batched, fp16-native; M=256,N=256,K=128)
    gemm_h16n<<<dim3(CK / 128, CK / 128, NCC), 256>>>(bch, bch + NST, cb,
        NST, 2 * NST, 2 * NST, CK, CK, (long)CK * 2 * NST, (long)CK * 2 * NST, (long)CK * CK);

    // 5) chunk states (tensor-core, LDSM)
    k_states_mma<<<NCC * NH, 256>>>(xbc, dt, dacs, st);

    // 6) inter-chunk scan (4x parallelism)
    k_scan<<<2 * NH * 4, 256>>>(st, dacs, pv);

    // 7) Y = Y_diag + Y_off + skip, gated  (tensor-core, LDSM)
    k_y_mma<<<NCC * NH, 256>>>(xbc, zx, dt, dacs, cb, pv, Dsk, y);

    // 8) RMSNorm -> fp16
    k_rms<<<TOK, 256>>>(y, nw, yh);

    // 9) out_proj: out = yh @ Wout^T  (M=4096, N=2048, K=4096)
    gemm_h16n<<<dim3(DMODEL / 128, TOK / 128, 1), 256>>>(yh, wouth, out,
        DINNER, DINNER, DINNER, DMODEL, DMODEL, 0, 0, 0);
}